// round 1
// baseline (speedup 1.0000x reference)
#include <cuda_runtime.h>
#include <cstdint>

// Problem constants (fixed by the dataset)
#define KDIM 4096
#define CDIM 4096
#define GRPS 32
#define GSIZE 128           // CDIM / GRPS
#define EPSV 1e-5f

// Tile config
#define BM 128
#define BN 128              // == GSIZE: one GroupNorm group per block column
#define BK 32
#define LDSS 132            // BM + 4 pad (keeps 16B alignment, breaks bank conflicts)
#define NTHREADS 256
#define TMV 8
#define TNV 8

typedef unsigned long long u64;

__device__ __forceinline__ u64 ffma2(u64 a, u64 b, u64 c) {
    u64 d;
    asm("fma.rn.f32x2 %0, %1, %2, %3;" : "=l"(d) : "l"(a), "l"(b), "l"(c));
    return d;
}
__device__ __forceinline__ u64 pack2(float x) {
    u64 d;
    asm("mov.b64 %0, {%1, %1};" : "=l"(d) : "f"(x));
    return d;
}
__device__ __forceinline__ u64 packxy(float lo, float hi) {
    u64 d;
    asm("mov.b64 %0, {%1, %2};" : "=l"(d) : "f"(lo), "f"(hi));
    return d;
}
__device__ __forceinline__ void unpack2(u64 v, float& lo, float& hi) {
    asm("mov.b64 {%0, %1}, %2;" : "=f"(lo), "=f"(hi) : "l"(v));
}
__device__ __forceinline__ float sigmoidf_(float x) {
    return 1.0f / (1.0f + expf(-x));
}

__global__ void __launch_bounds__(NTHREADS, 1)
fused_lin_gn_swish(const float* __restrict__ x,
                   const float* __restrict__ w,
                   const float* __restrict__ bias,
                   const float* __restrict__ gnw,
                   const float* __restrict__ gnb,
                   const float* __restrict__ mw,
                   float* __restrict__ out) {
    extern __shared__ float smem[];
    // layout: As[2][BK][LDSS], Bs[2][BK][LDSS]
    float* AsBase = smem;
    float* BsBase = smem + 2 * BK * LDSS;

    const int tid = threadIdx.x;
    const int tn  = tid & 15;        // 0..15  (column quadrant)
    const int tm  = tid >> 4;        // 0..15  (row quadrant)

    const int rowBase = blockIdx.y * BM;
    const int colBase = blockIdx.x * BN;

    const float* Aptr = x + (size_t)rowBase * KDIM;
    const float* Bptr = w + (size_t)colBase * KDIM;

    // 8x8 accumulators as 8x4 packed f32x2 pairs: acc[mi][jp] = (c[mi][2jp], c[mi][2jp+1])
    u64 acc[TMV][TNV / 2];
#pragma unroll
    for (int i = 0; i < TMV; i++)
#pragma unroll
        for (int j = 0; j < TNV / 2; j++) acc[i][j] = 0ull;

    float4 areg[4], breg[4];

    const int r_ld  = tid >> 3;      // 0..31 rows loaded per i-step at stride 32... (idx>>3)
    const int k4_ld = tid & 7;       // float4 column within BK

    // ---- load tile 0 into regs ----
    {
        const int kbase = 0;
#pragma unroll
        for (int i = 0; i < 4; i++) {
            int r = r_ld + i * 32;
            areg[i] = *(const float4*)(Aptr + (size_t)r * KDIM + kbase + k4_ld * 4);
            breg[i] = *(const float4*)(Bptr + (size_t)r * KDIM + kbase + k4_ld * 4);
        }
    }
    // ---- store tile 0 (transposed) ----
    {
        float* As = AsBase;
        float* Bs = BsBase;
#pragma unroll
        for (int i = 0; i < 4; i++) {
            int r = r_ld + i * 32;
            int kc = k4_ld * 4;
            As[(kc + 0) * LDSS + r] = areg[i].x;
            As[(kc + 1) * LDSS + r] = areg[i].y;
            As[(kc + 2) * LDSS + r] = areg[i].z;
            As[(kc + 3) * LDSS + r] = areg[i].w;
            Bs[(kc + 0) * LDSS + r] = breg[i].x;
            Bs[(kc + 1) * LDSS + r] = breg[i].y;
            Bs[(kc + 2) * LDSS + r] = breg[i].z;
            Bs[(kc + 3) * LDSS + r] = breg[i].w;
        }
    }
    __syncthreads();

    const int NT = KDIM / BK;
    int buf = 0;
    for (int kt = 0; kt < NT; kt++) {
        // prefetch next tile into registers
        if (kt + 1 < NT) {
            const int kbase = (kt + 1) * BK;
#pragma unroll
            for (int i = 0; i < 4; i++) {
                int r = r_ld + i * 32;
                areg[i] = *(const float4*)(Aptr + (size_t)r * KDIM + kbase + k4_ld * 4);
                breg[i] = *(const float4*)(Bptr + (size_t)r * KDIM + kbase + k4_ld * 4);
            }
        }

        // compute on current buffer
        {
            const float* As = AsBase + buf * BK * LDSS;
            const float* Bs = BsBase + buf * BK * LDSS;
#pragma unroll 8
            for (int k = 0; k < BK; k++) {
                const float4 a0 = *(const float4*)(As + k * LDSS + tm * TMV);
                const float4 a1 = *(const float4*)(As + k * LDSS + tm * TMV + 4);
                const float4 b0 = *(const float4*)(Bs + k * LDSS + tn * TNV);
                const float4 b1 = *(const float4*)(Bs + k * LDSS + tn * TNV + 4);

                u64 ap[TMV];
                ap[0] = pack2(a0.x); ap[1] = pack2(a0.y);
                ap[2] = pack2(a0.z); ap[3] = pack2(a0.w);
                ap[4] = pack2(a1.x); ap[5] = pack2(a1.y);
                ap[6] = pack2(a1.z); ap[7] = pack2(a1.w);

                u64 bp[TNV / 2];
                bp[0] = packxy(b0.x, b0.y);
                bp[1] = packxy(b0.z, b0.w);
                bp[2] = packxy(b1.x, b1.y);
                bp[3] = packxy(b1.z, b1.w);

#pragma unroll
                for (int mi = 0; mi < TMV; mi++)
#pragma unroll
                    for (int j = 0; j < TNV / 2; j++)
                        acc[mi][j] = ffma2(ap[mi], bp[j], acc[mi][j]);
            }
        }

        // write prefetched tile into the other buffer
        if (kt + 1 < NT) {
            float* As = AsBase + (buf ^ 1) * BK * LDSS;
            float* Bs = BsBase + (buf ^ 1) * BK * LDSS;
#pragma unroll
            for (int i = 0; i < 4; i++) {
                int r = r_ld + i * 32;
                int kc = k4_ld * 4;
                As[(kc + 0) * LDSS + r] = areg[i].x;
                As[(kc + 1) * LDSS + r] = areg[i].y;
                As[(kc + 2) * LDSS + r] = areg[i].z;
                As[(kc + 3) * LDSS + r] = areg[i].w;
                Bs[(kc + 0) * LDSS + r] = breg[i].x;
                Bs[(kc + 1) * LDSS + r] = breg[i].y;
                Bs[(kc + 2) * LDSS + r] = breg[i].z;
                Bs[(kc + 3) * LDSS + r] = breg[i].w;
            }
            __syncthreads();
            buf ^= 1;
        }
    }

    // ================= fused epilogue =================
    // Unpack, add bias. Block column == one GroupNorm group (BN == GSIZE).
    const int cB = colBase + tn * TNV;
    float biasv[TNV], gnwv[TNV], gnbv[TNV], mwv[TNV];
    {
        float4 t;
        t = *(const float4*)(bias + cB);     biasv[0]=t.x; biasv[1]=t.y; biasv[2]=t.z; biasv[3]=t.w;
        t = *(const float4*)(bias + cB + 4); biasv[4]=t.x; biasv[5]=t.y; biasv[6]=t.z; biasv[7]=t.w;
        t = *(const float4*)(gnw + cB);      gnwv[0]=t.x; gnwv[1]=t.y; gnwv[2]=t.z; gnwv[3]=t.w;
        t = *(const float4*)(gnw + cB + 4);  gnwv[4]=t.x; gnwv[5]=t.y; gnwv[6]=t.z; gnwv[7]=t.w;
        t = *(const float4*)(gnb + cB);      gnbv[0]=t.x; gnbv[1]=t.y; gnbv[2]=t.z; gnbv[3]=t.w;
        t = *(const float4*)(gnb + cB + 4);  gnbv[4]=t.x; gnbv[5]=t.y; gnbv[6]=t.z; gnbv[7]=t.w;
        t = *(const float4*)(mw + cB);       mwv[0]=t.x; mwv[1]=t.y; mwv[2]=t.z; mwv[3]=t.w;
        t = *(const float4*)(mw + cB + 4);   mwv[4]=t.x; mwv[5]=t.y; mwv[6]=t.z; mwv[7]=t.w;
    }

    float c[TMV][TNV];
#pragma unroll
    for (int mi = 0; mi < TMV; mi++) {
#pragma unroll
        for (int j = 0; j < TNV / 2; j++) {
            float lo, hi;
            unpack2(acc[mi][j], lo, hi);
            c[mi][2 * j]     = lo + biasv[2 * j];
            c[mi][2 * j + 1] = hi + biasv[2 * j + 1];
        }
    }

    // Per-row partial sums over this thread's 8 columns
    float sum[TMV], sq[TMV];
#pragma unroll
    for (int mi = 0; mi < TMV; mi++) {
        float s = 0.f, q = 0.f;
#pragma unroll
        for (int ni = 0; ni < TNV; ni++) {
            float v = c[mi][ni];
            s += v;
            q += v * v;
        }
        sum[mi] = s; sq[mi] = q;
    }
    // Reduce across the 16 tn-threads of each row (xor<16 stays in half-warp)
#pragma unroll
    for (int off = 8; off >= 1; off >>= 1) {
#pragma unroll
        for (int mi = 0; mi < TMV; mi++) {
            sum[mi] += __shfl_xor_sync(0xffffffffu, sum[mi], off);
            sq[mi]  += __shfl_xor_sync(0xffffffffu, sq[mi],  off);
        }
    }

    const float invn = 1.0f / (float)GSIZE;
#pragma unroll
    for (int mi = 0; mi < TMV; mi++) {
        const float mean = sum[mi] * invn;
        const float var  = sq[mi] * invn - mean * mean;
        const float rstd = rsqrtf(var + EPSV);

        float o[TNV];
#pragma unroll
        for (int ni = 0; ni < TNV; ni++) {
            float hn = (c[mi][ni] - mean) * rstd;
            hn = hn * gnwv[ni] + gnbv[ni];
            float x1 = hn * sigmoidf_(hn);
            float x2 = x1 * mwv[ni];
            o[ni] = x2 * sigmoidf_(x2);
        }
        const size_t orow = (size_t)(rowBase + tm * TMV + mi) * CDIM + cB;
        *(float4*)(out + orow)     = make_float4(o[0], o[1], o[2], o[3]);
        *(float4*)(out + orow + 4) = make_float4(o[4], o[5], o[6], o[7]);
    }
}

extern "C" void kernel_launch(void* const* d_in, const int* in_sizes, int n_in,
                              void* d_out, int out_size) {
    const float* x    = (const float*)d_in[0];
    const float* w    = (const float*)d_in[1];
    const float* bias = (const float*)d_in[2];
    const float* gnw  = (const float*)d_in[3];
    const float* gnb  = (const float*)d_in[4];
    const float* mw   = (const float*)d_in[5];
    float* out = (float*)d_out;

    const int Bdim = in_sizes[0] / KDIM;   // 8192

    const size_t smem = (size_t)2 * 2 * BK * LDSS * sizeof(float);  // 67,584 B
    cudaFuncSetAttribute(fused_lin_gn_swish,
                         cudaFuncAttributeMaxDynamicSharedMemorySize, (int)smem);

    dim3 grid(CDIM / BN, Bdim / BM);   // 32 x 64
    dim3 block(NTHREADS);
    fused_lin_gn_swish<<<grid, block, smem>>>(x, w, bias, gnw, gnb, mw, out);
}

// round 2
// speedup vs baseline: 1.0000x; 1.0000x over previous
#include <cuda_runtime.h>
#include <cstdint>

// Problem constants (fixed by the dataset)
#define KDIM 4096
#define CDIM 4096
#define GRPS 32
#define GSIZE 128           // CDIM / GRPS
#define EPSV 1e-5f

// Tile config
#define BM 128
#define BN 128              // == GSIZE: one GroupNorm group per block column
#define BK 32
#define LDSS 132            // BM + 4 pad (keeps 16B alignment, breaks bank conflicts)
#define NTHREADS 256
#define TMV 8
#define TNV 8

typedef unsigned long long u64;

__device__ __forceinline__ u64 ffma2(u64 a, u64 b, u64 c) {
    u64 d;
    asm("fma.rn.f32x2 %0, %1, %2, %3;" : "=l"(d) : "l"(a), "l"(b), "l"(c));
    return d;
}
__device__ __forceinline__ u64 pack2(float x) {
    u64 d;
    asm("mov.b64 %0, {%1, %1};" : "=l"(d) : "f"(x));
    return d;
}
__device__ __forceinline__ u64 packxy(float lo, float hi) {
    u64 d;
    asm("mov.b64 %0, {%1, %2};" : "=l"(d) : "f"(lo), "f"(hi));
    return d;
}
__device__ __forceinline__ void unpack2(u64 v, float& lo, float& hi) {
    asm("mov.b64 {%0, %1}, %2;" : "=f"(lo), "=f"(hi) : "l"(v));
}
__device__ __forceinline__ float sigmoidf_(float x) {
    return 1.0f / (1.0f + expf(-x));
}

__global__ void __launch_bounds__(NTHREADS, 1)
fused_lin_gn_swish(const float* __restrict__ x,
                   const float* __restrict__ w,
                   const float* __restrict__ bias,
                   const float* __restrict__ gnw,
                   const float* __restrict__ gnb,
                   const float* __restrict__ mw,
                   float* __restrict__ out) {
    extern __shared__ float smem[];
    // layout: As[2][BK][LDSS], Bs[2][BK][LDSS]
    float* AsBase = smem;
    float* BsBase = smem + 2 * BK * LDSS;

    const int tid = threadIdx.x;
    const int tn  = tid & 15;        // 0..15  (column quadrant)
    const int tm  = tid >> 4;        // 0..15  (row quadrant)

    const int rowBase = blockIdx.y * BM;
    const int colBase = blockIdx.x * BN;

    const float* Aptr = x + (size_t)rowBase * KDIM;
    const float* Bptr = w + (size_t)colBase * KDIM;

    // 8x8 accumulators as 8x4 packed f32x2 pairs: acc[mi][jp] = (c[mi][2jp], c[mi][2jp+1])
    u64 acc[TMV][TNV / 2];
#pragma unroll
    for (int i = 0; i < TMV; i++)
#pragma unroll
        for (int j = 0; j < TNV / 2; j++) acc[i][j] = 0ull;

    float4 areg[4], breg[4];

    const int r_ld  = tid >> 3;      // 0..31 rows loaded per i-step at stride 32... (idx>>3)
    const int k4_ld = tid & 7;       // float4 column within BK

    // ---- load tile 0 into regs ----
    {
        const int kbase = 0;
#pragma unroll
        for (int i = 0; i < 4; i++) {
            int r = r_ld + i * 32;
            areg[i] = *(const float4*)(Aptr + (size_t)r * KDIM + kbase + k4_ld * 4);
            breg[i] = *(const float4*)(Bptr + (size_t)r * KDIM + kbase + k4_ld * 4);
        }
    }
    // ---- store tile 0 (transposed) ----
    {
        float* As = AsBase;
        float* Bs = BsBase;
#pragma unroll
        for (int i = 0; i < 4; i++) {
            int r = r_ld + i * 32;
            int kc = k4_ld * 4;
            As[(kc + 0) * LDSS + r] = areg[i].x;
            As[(kc + 1) * LDSS + r] = areg[i].y;
            As[(kc + 2) * LDSS + r] = areg[i].z;
            As[(kc + 3) * LDSS + r] = areg[i].w;
            Bs[(kc + 0) * LDSS + r] = breg[i].x;
            Bs[(kc + 1) * LDSS + r] = breg[i].y;
            Bs[(kc + 2) * LDSS + r] = breg[i].z;
            Bs[(kc + 3) * LDSS + r] = breg[i].w;
        }
    }
    __syncthreads();

    const int NT = KDIM / BK;
    int buf = 0;
    for (int kt = 0; kt < NT; kt++) {
        // prefetch next tile into registers
        if (kt + 1 < NT) {
            const int kbase = (kt + 1) * BK;
#pragma unroll
            for (int i = 0; i < 4; i++) {
                int r = r_ld + i * 32;
                areg[i] = *(const float4*)(Aptr + (size_t)r * KDIM + kbase + k4_ld * 4);
                breg[i] = *(const float4*)(Bptr + (size_t)r * KDIM + kbase + k4_ld * 4);
            }
        }

        // compute on current buffer
        {
            const float* As = AsBase + buf * BK * LDSS;
            const float* Bs = BsBase + buf * BK * LDSS;
#pragma unroll 8
            for (int k = 0; k < BK; k++) {
                const float4 a0 = *(const float4*)(As + k * LDSS + tm * TMV);
                const float4 a1 = *(const float4*)(As + k * LDSS + tm * TMV + 4);
                const float4 b0 = *(const float4*)(Bs + k * LDSS + tn * TNV);
                const float4 b1 = *(const float4*)(Bs + k * LDSS + tn * TNV + 4);

                u64 ap[TMV];
                ap[0] = pack2(a0.x); ap[1] = pack2(a0.y);
                ap[2] = pack2(a0.z); ap[3] = pack2(a0.w);
                ap[4] = pack2(a1.x); ap[5] = pack2(a1.y);
                ap[6] = pack2(a1.z); ap[7] = pack2(a1.w);

                u64 bp[TNV / 2];
                bp[0] = packxy(b0.x, b0.y);
                bp[1] = packxy(b0.z, b0.w);
                bp[2] = packxy(b1.x, b1.y);
                bp[3] = packxy(b1.z, b1.w);

#pragma unroll
                for (int mi = 0; mi < TMV; mi++)
#pragma unroll
                    for (int j = 0; j < TNV / 2; j++)
                        acc[mi][j] = ffma2(ap[mi], bp[j], acc[mi][j]);
            }
        }

        // write prefetched tile into the other buffer
        if (kt + 1 < NT) {
            float* As = AsBase + (buf ^ 1) * BK * LDSS;
            float* Bs = BsBase + (buf ^ 1) * BK * LDSS;
#pragma unroll
            for (int i = 0; i < 4; i++) {
                int r = r_ld + i * 32;
                int kc = k4_ld * 4;
                As[(kc + 0) * LDSS + r] = areg[i].x;
                As[(kc + 1) * LDSS + r] = areg[i].y;
                As[(kc + 2) * LDSS + r] = areg[i].z;
                As[(kc + 3) * LDSS + r] = areg[i].w;
                Bs[(kc + 0) * LDSS + r] = breg[i].x;
                Bs[(kc + 1) * LDSS + r] = breg[i].y;
                Bs[(kc + 2) * LDSS + r] = breg[i].z;
                Bs[(kc + 3) * LDSS + r] = breg[i].w;
            }
            __syncthreads();
            buf ^= 1;
        }
    }

    // ================= fused epilogue =================
    // Unpack, add bias. Block column == one GroupNorm group (BN == GSIZE).
    const int cB = colBase + tn * TNV;
    float biasv[TNV], gnwv[TNV], gnbv[TNV], mwv[TNV];
    {
        float4 t;
        t = *(const float4*)(bias + cB);     biasv[0]=t.x; biasv[1]=t.y; biasv[2]=t.z; biasv[3]=t.w;
        t = *(const float4*)(bias + cB + 4); biasv[4]=t.x; biasv[5]=t.y; biasv[6]=t.z; biasv[7]=t.w;
        t = *(const float4*)(gnw + cB);      gnwv[0]=t.x; gnwv[1]=t.y; gnwv[2]=t.z; gnwv[3]=t.w;
        t = *(const float4*)(gnw + cB + 4);  gnwv[4]=t.x; gnwv[5]=t.y; gnwv[6]=t.z; gnwv[7]=t.w;
        t = *(const float4*)(gnb + cB);      gnbv[0]=t.x; gnbv[1]=t.y; gnbv[2]=t.z; gnbv[3]=t.w;
        t = *(const float4*)(gnb + cB + 4);  gnbv[4]=t.x; gnbv[5]=t.y; gnbv[6]=t.z; gnbv[7]=t.w;
        t = *(const float4*)(mw + cB);       mwv[0]=t.x; mwv[1]=t.y; mwv[2]=t.z; mwv[3]=t.w;
        t = *(const float4*)(mw + cB + 4);   mwv[4]=t.x; mwv[5]=t.y; mwv[6]=t.z; mwv[7]=t.w;
    }

    float c[TMV][TNV];
#pragma unroll
    for (int mi = 0; mi < TMV; mi++) {
#pragma unroll
        for (int j = 0; j < TNV / 2; j++) {
            float lo, hi;
            unpack2(acc[mi][j], lo, hi);
            c[mi][2 * j]     = lo + biasv[2 * j];
            c[mi][2 * j + 1] = hi + biasv[2 * j + 1];
        }
    }

    // Per-row partial sums over this thread's 8 columns
    float sum[TMV], sq[TMV];
#pragma unroll
    for (int mi = 0; mi < TMV; mi++) {
        float s = 0.f, q = 0.f;
#pragma unroll
        for (int ni = 0; ni < TNV; ni++) {
            float v = c[mi][ni];
            s += v;
            q += v * v;
        }
        sum[mi] = s; sq[mi] = q;
    }
    // Reduce across the 16 tn-threads of each row (xor<16 stays in half-warp)
#pragma unroll
    for (int off = 8; off >= 1; off >>= 1) {
#pragma unroll
        for (int mi = 0; mi < TMV; mi++) {
            sum[mi] += __shfl_xor_sync(0xffffffffu, sum[mi], off);
            sq[mi]  += __shfl_xor_sync(0xffffffffu, sq[mi],  off);
        }
    }

    const float invn = 1.0f / (float)GSIZE;
#pragma unroll
    for (int mi = 0; mi < TMV; mi++) {
        const float mean = sum[mi] * invn;
        const float var  = sq[mi] * invn - mean * mean;
        const float rstd = rsqrtf(var + EPSV);

        float o[TNV];
#pragma unroll
        for (int ni = 0; ni < TNV; ni++) {
            float hn = (c[mi][ni] - mean) * rstd;
            hn = hn * gnwv[ni] + gnbv[ni];
            float x1 = hn * sigmoidf_(hn);
            float x2 = x1 * mwv[ni];
            o[ni] = x2 * sigmoidf_(x2);
        }
        const size_t orow = (size_t)(rowBase + tm * TMV + mi) * CDIM + cB;
        *(float4*)(out + orow)     = make_float4(o[0], o[1], o[2], o[3]);
        *(float4*)(out + orow + 4) = make_float4(o[4], o[5], o[6], o[7]);
    }
}

extern "C" void kernel_launch(void* const* d_in, const int* in_sizes, int n_in,
                              void* d_out, int out_size) {
    const float* x    = (const float*)d_in[0];
    const float* w    = (const float*)d_in[1];
    const float* bias = (const float*)d_in[2];
    const float* gnw  = (const float*)d_in[3];
    const float* gnb  = (const float*)d_in[4];
    const float* mw   = (const float*)d_in[5];
    float* out = (float*)d_out;

    const int Bdim = in_sizes[0] / KDIM;   // 8192

    const size_t smem = (size_t)2 * 2 * BK * LDSS * sizeof(float);  // 67,584 B
    cudaFuncSetAttribute(fused_lin_gn_swish,
                         cudaFuncAttributeMaxDynamicSharedMemorySize, (int)smem);

    dim3 grid(CDIM / BN, Bdim / BM);   // 32 x 64
    dim3 block(NTHREADS);
    fused_lin_gn_swish<<<grid, block, smem>>>(x, w, bias, gnw, gnb, mw, out);
}

// round 4
// speedup vs baseline: 1.6065x; 1.6065x over previous
#include <cuda_runtime.h>
#include <cuda_bf16.h>
#include <cstdint>

#define KDIM 4096
#define CDIM 4096
#define BROWS 8192
#define EPSV 1e-5f

#define BMt 128
#define BNt 128
#define BKt 32
#define TPB 256
#define NSTG 4
#define STG_B 32768         // Ah(8K) Al(8K) Bh(8K) Bl(8K)
#define NKT (KDIM / BKt)    // 128

// bf16 hi/lo scratch (device globals: sanctioned no-alloc workaround)
__device__ __nv_bfloat16 g_xhi[(size_t)BROWS * KDIM];
__device__ __nv_bfloat16 g_xlo[(size_t)BROWS * KDIM];
__device__ __nv_bfloat16 g_whi[(size_t)CDIM * KDIM];
__device__ __nv_bfloat16 g_wlo[(size_t)CDIM * KDIM];

// ---------------- helpers ----------------
__device__ __forceinline__ uint32_t s2u(const void* p) {
    uint32_t a;
    asm("{ .reg .u64 t; cvta.to.shared.u64 t, %1; cvt.u32.u64 %0, t; }"
        : "=r"(a) : "l"(p));
    return a;
}
__device__ __forceinline__ void cp16(uint32_t d, const void* s) {
    asm volatile("cp.async.cg.shared.global [%0], [%1], 16;" :: "r"(d), "l"(s));
}
__device__ __forceinline__ void cp_commit() {
    asm volatile("cp.async.commit_group;" ::: "memory");
}
template <int N> __device__ __forceinline__ void cp_wait() {
    asm volatile("cp.async.wait_group %0;" :: "n"(N) : "memory");
}
__device__ __forceinline__ void ldsm4(uint32_t* r, uint32_t a) {
    asm volatile("ldmatrix.sync.aligned.m8n8.x4.shared.b16 {%0,%1,%2,%3}, [%4];"
        : "=r"(r[0]), "=r"(r[1]), "=r"(r[2]), "=r"(r[3]) : "r"(a));
}
__device__ __forceinline__ void mma16816(float* d, const uint32_t* a,
                                         uint32_t b0, uint32_t b1) {
    asm volatile("mma.sync.aligned.m16n8k16.row.col.f32.bf16.bf16.f32 "
        "{%0,%1,%2,%3}, {%4,%5,%6,%7}, {%8,%9}, {%0,%1,%2,%3};"
        : "+f"(d[0]), "+f"(d[1]), "+f"(d[2]), "+f"(d[3])
        : "r"(a[0]), "r"(a[1]), "r"(a[2]), "r"(a[3]), "r"(b0), "r"(b1));
}

// ---------------- convert kernel ----------------
__global__ void __launch_bounds__(256)
k_convert(const float* __restrict__ src, __nv_bfloat16* __restrict__ hi,
          __nv_bfloat16* __restrict__ lo, size_t n4) {
    size_t i = (size_t)blockIdx.x * blockDim.x + threadIdx.x;
    size_t stride = (size_t)gridDim.x * blockDim.x;
    for (; i < n4; i += stride) {
        float4 v = ((const float4*)src)[i];
        __nv_bfloat16 h0 = __float2bfloat16(v.x), h1 = __float2bfloat16(v.y);
        __nv_bfloat16 h2 = __float2bfloat16(v.z), h3 = __float2bfloat16(v.w);
        __nv_bfloat16 l0 = __float2bfloat16(v.x - __bfloat162float(h0));
        __nv_bfloat16 l1 = __float2bfloat16(v.y - __bfloat162float(h1));
        __nv_bfloat16 l2 = __float2bfloat16(v.z - __bfloat162float(h2));
        __nv_bfloat16 l3 = __float2bfloat16(v.w - __bfloat162float(h3));
        ((__nv_bfloat162*)hi)[i * 2 + 0] = __halves2bfloat162(h0, h1);
        ((__nv_bfloat162*)hi)[i * 2 + 1] = __halves2bfloat162(h2, h3);
        ((__nv_bfloat162*)lo)[i * 2 + 0] = __halves2bfloat162(l0, l1);
        ((__nv_bfloat162*)lo)[i * 2 + 1] = __halves2bfloat162(l2, l3);
    }
}

// ---------------- fused GEMM (HMMA bf16x3) ----------------
__global__ void __launch_bounds__(TPB, 1)
gemm_hmma(const float* __restrict__ bias, const float* __restrict__ gnw,
          const float* __restrict__ gnb, const float* __restrict__ mw,
          float* __restrict__ out) {
    extern __shared__ char smraw[];
    const uint32_t smb = s2u(smraw);

    const int tid = threadIdx.x;
    const int lane = tid & 31;
    const int wid = tid >> 5;
    const int warpM = wid >> 2;     // 0..1
    const int warpN = wid & 3;      // 0..3
    const int rowBase = blockIdx.y * BMt;
    const int colBase = blockIdx.x * BNt;

    // ---- loader mapping: 4 tiles (Ah,Al,Bh,Bl) x 64 threads; 2 rows each ----
    const int ltile = tid >> 6;
    const int lrow = (tid & 63) * 2;
    const __nv_bfloat16* lsrc =
        (ltile == 0) ? g_xhi : (ltile == 1) ? g_xlo : (ltile == 2) ? g_whi : g_wlo;
    const int lbase = (ltile < 2) ? rowBase : colBase;
    const char* lp0 = (const char*)(lsrc + (size_t)(lbase + lrow) * KDIM);
    const char* lp1 = lp0 + (size_t)KDIM * 2;
    const uint32_t ldst = smb + ltile * 8192 + lrow * 64;
    uint32_t swzA[4], swzB[4];   // swizzled chunk byte offsets for row0 / row1
#pragma unroll
    for (int c = 0; c < 4; c++) {
        swzA[c] = (uint32_t)((c ^ (lrow & 3)) * 16);
        swzB[c] = (uint32_t)(((c ^ ((lrow + 1) & 3)) * 16) + 64);
    }

#define LOAD_STAGE(kt_, s_) do {                                       \
        const char* p0_ = lp0 + (size_t)(kt_) * 64;                    \
        const char* p1_ = lp1 + (size_t)(kt_) * 64;                    \
        uint32_t d_ = ldst + (uint32_t)(s_) * STG_B;                   \
        cp16(d_ + swzA[0], p0_);      cp16(d_ + swzA[1], p0_ + 16);    \
        cp16(d_ + swzA[2], p0_ + 32); cp16(d_ + swzA[3], p0_ + 48);    \
        cp16(d_ + swzB[0], p1_);      cp16(d_ + swzB[1], p1_ + 16);    \
        cp16(d_ + swzB[2], p1_ + 32); cp16(d_ + swzB[3], p1_ + 48);    \
        cp_commit();                                                   \
    } while (0)

    // ---- ldmatrix lane address precompute ----
    uint32_t arowoff[4], amask[4];
#pragma unroll
    for (int mt = 0; mt < 4; mt++) {
        int r = warpM * 64 + mt * 16 + (lane & 7) + ((lane >> 3) & 1) * 8;
        arowoff[mt] = (uint32_t)(r * 64);
        amask[mt] = (uint32_t)(r & 3);
    }
    const uint32_t asel = (uint32_t)((lane >> 4) & 1);
    uint32_t browoff[2], bmask[2];
#pragma unroll
    for (int ng = 0; ng < 2; ng++) {
        int r = warpN * 32 + ng * 16 + (lane & 7) + ((lane >> 4) & 1) * 8;
        browoff[ng] = (uint32_t)(r * 64);
        bmask[ng] = (uint32_t)(r & 3);
    }
    const uint32_t bsel = (uint32_t)((lane >> 3) & 1);

    float acc[16][4];
#pragma unroll
    for (int i = 0; i < 16; i++)
#pragma unroll
        for (int j = 0; j < 4; j++) acc[i][j] = 0.f;

    // prologue: stages 0..2
    LOAD_STAGE(0, 0);
    LOAD_STAGE(1, 1);
    LOAD_STAGE(2, 2);

    for (int kt = 0; kt < NKT; kt++) {
        if (kt < NKT - 2) cp_wait<2>(); else cp_wait<0>();
        __syncthreads();

        if (kt + 3 < NKT) LOAD_STAGE(kt + 3, (kt + 3) & 3);

        const uint32_t Ab = smb + (uint32_t)(kt & 3) * STG_B;
        const uint32_t Bb = Ab + 16384;
#pragma unroll
        for (int k16 = 0; k16 < 2; k16++) {
            uint32_t ah[4][4], al[4][4], bh[2][4], bl[2][4];
#pragma unroll
            for (int mt = 0; mt < 4; mt++) {
                uint32_t ad = Ab + arowoff[mt]
                            + ((((uint32_t)k16 * 2 + asel) ^ amask[mt]) << 4);
                ldsm4(ah[mt], ad);
                ldsm4(al[mt], ad + 8192);
            }
#pragma unroll
            for (int ng = 0; ng < 2; ng++) {
                uint32_t bd = Bb + browoff[ng]
                            + ((((uint32_t)k16 * 2 + bsel) ^ bmask[ng]) << 4);
                ldsm4(bh[ng], bd);
                ldsm4(bl[ng], bd + 8192);
            }
#pragma unroll
            for (int mt = 0; mt < 4; mt++)
#pragma unroll
                for (int nt = 0; nt < 4; nt++) {
                    const int ng = nt >> 1, o = (nt & 1) * 2;
                    mma16816(acc[mt * 4 + nt], ah[mt], bh[ng][o], bh[ng][o + 1]);
                    mma16816(acc[mt * 4 + nt], ah[mt], bl[ng][o], bl[ng][o + 1]);
                    mma16816(acc[mt * 4 + nt], al[mt], bh[ng][o], bh[ng][o + 1]);
                }
        }
    }

    // ---------------- fused epilogue ----------------
    // bias add
    float biasv[8];
#pragma unroll
    for (int nt = 0; nt < 4; nt++) {
        int c0 = colBase + warpN * 32 + nt * 8 + 2 * (lane & 3);
        biasv[nt * 2]     = __ldg(bias + c0);
        biasv[nt * 2 + 1] = __ldg(bias + c0 + 1);
    }
#pragma unroll
    for (int mt = 0; mt < 4; mt++)
#pragma unroll
        for (int nt = 0; nt < 4; nt++) {
            acc[mt * 4 + nt][0] += biasv[nt * 2];
            acc[mt * 4 + nt][1] += biasv[nt * 2 + 1];
            acc[mt * 4 + nt][2] += biasv[nt * 2];
            acc[mt * 4 + nt][3] += biasv[nt * 2 + 1];
        }

    // per-thread partial row sums over this warp's 32 columns
    float rs[8], rq[8];
#pragma unroll
    for (int mt = 0; mt < 4; mt++) {
        float s0 = 0.f, q0 = 0.f, s1 = 0.f, q1 = 0.f;
#pragma unroll
        for (int nt = 0; nt < 4; nt++) {
            float v;
            v = acc[mt * 4 + nt][0]; s0 += v; q0 += v * v;
            v = acc[mt * 4 + nt][1]; s0 += v; q0 += v * v;
            v = acc[mt * 4 + nt][2]; s1 += v; q1 += v * v;
            v = acc[mt * 4 + nt][3]; s1 += v; q1 += v * v;
        }
        rs[mt * 2] = s0; rq[mt * 2] = q0;
        rs[mt * 2 + 1] = s1; rq[mt * 2 + 1] = q1;
    }
#pragma unroll
    for (int off = 1; off <= 2; off <<= 1)
#pragma unroll
        for (int i = 0; i < 8; i++) {
            rs[i] += __shfl_xor_sync(0xffffffffu, rs[i], off);
            rq[i] += __shfl_xor_sync(0xffffffffu, rq[i], off);
        }

    // cross-warp combine via smem (reuse stage 0; safe: last read of stage 0
    // was kt=124, protected by the per-iteration syncthreads since then)
    float2* red = (float2*)smraw;        // [128][4]
    __syncthreads();
    if ((lane & 3) == 0) {
#pragma unroll
        for (int mt = 0; mt < 4; mt++)
#pragma unroll
            for (int h = 0; h < 2; h++) {
                int rowL = warpM * 64 + mt * 16 + (lane >> 2) + h * 8;
                red[rowL * 4 + warpN] = make_float2(rs[mt * 2 + h], rq[mt * 2 + h]);
            }
    }
    __syncthreads();

    float meanv[8], rstdv[8];
#pragma unroll
    for (int mt = 0; mt < 4; mt++)
#pragma unroll
        for (int h = 0; h < 2; h++) {
            int rowL = warpM * 64 + mt * 16 + (lane >> 2) + h * 8;
            float s = 0.f, q = 0.f;
#pragma unroll
            for (int wn = 0; wn < 4; wn++) {
                float2 t = red[rowL * 4 + wn];
                s += t.x; q += t.y;
            }
            float m = s * (1.0f / 128.0f);
            float var = q * (1.0f / 128.0f) - m * m;
            meanv[mt * 2 + h] = m;
            rstdv[mt * 2 + h] = rsqrtf(var + EPSV);
        }

    // scales
    float gwv[8], gbv[8], mwv[8];
#pragma unroll
    for (int nt = 0; nt < 4; nt++) {
        int c0 = colBase + warpN * 32 + nt * 8 + 2 * (lane & 3);
        gwv[nt * 2] = __ldg(gnw + c0);   gwv[nt * 2 + 1] = __ldg(gnw + c0 + 1);
        gbv[nt * 2] = __ldg(gnb + c0);   gbv[nt * 2 + 1] = __ldg(gnb + c0 + 1);
        mwv[nt * 2] = __ldg(mw + c0);    mwv[nt * 2 + 1] = __ldg(mw + c0 + 1);
    }

#pragma unroll
    for (int mt = 0; mt < 4; mt++)
#pragma unroll
        for (int h = 0; h < 2; h++) {
            const int r = rowBase + warpM * 64 + mt * 16 + (lane >> 2) + h * 8;
            const float m = meanv[mt * 2 + h];
            const float rstd = rstdv[mt * 2 + h];
#pragma unroll
            for (int nt = 0; nt < 4; nt++) {
                const int c0 = colBase + warpN * 32 + nt * 8 + 2 * (lane & 3);
                float o2[2];
#pragma unroll
                for (int j = 0; j < 2; j++) {
                    float v = acc[mt * 4 + nt][h * 2 + j];
                    float hn = (v - m) * rstd;
                    hn = fmaf(hn, gwv[nt * 2 + j], gbv[nt * 2 + j]);
                    float x1 = __fdividef(hn, 1.0f + __expf(-hn));
                    float x2 = x1 * mwv[nt * 2 + j];
                    o2[j] = __fdividef(x2, 1.0f + __expf(-x2));
                }
                *(float2*)(out + (size_t)r * CDIM + c0) = make_float2(o2[0], o2[1]);
            }
        }
}

extern "C" void kernel_launch(void* const* d_in, const int* in_sizes, int n_in,
                              void* d_out, int out_size) {
    const float* x    = (const float*)d_in[0];
    const float* w    = (const float*)d_in[1];
    const float* bias = (const float*)d_in[2];
    const float* gnw  = (const float*)d_in[3];
    const float* gnb  = (const float*)d_in[4];
    const float* mw   = (const float*)d_in[5];
    float* out = (float*)d_out;

    const int rows = in_sizes[0] / KDIM;   // 8192

    __nv_bfloat16 *xhi, *xlo, *whi, *wlo;
    cudaGetSymbolAddress((void**)&xhi, g_xhi);
    cudaGetSymbolAddress((void**)&xlo, g_xlo);
    cudaGetSymbolAddress((void**)&whi, g_whi);
    cudaGetSymbolAddress((void**)&wlo, g_wlo);

    k_convert<<<2048, 256>>>(x, xhi, xlo, (size_t)rows * KDIM / 4);
    k_convert<<<2048, 256>>>(w, whi, wlo, (size_t)CDIM * KDIM / 4);

    const int smem = NSTG * STG_B;     // 131072
    cudaFuncSetAttribute(gemm_hmma,
                         cudaFuncAttributeMaxDynamicSharedMemorySize, smem);

    dim3 grid(CDIM / BNt, rows / BMt);  // 32 x 64
    gemm_hmma<<<grid, TPB, smem>>>(bias, gnw, gnb, mw, out);
}